// round 6
// baseline (speedup 1.0000x reference)
#include <cuda_runtime.h>

// out[e,b,o] = sum_n x[e,b,n] * W[e,o,n] + b[e,o]
// E=50000, B=512, N=2, O=2. HBM streaming (~411 MB logical traffic).
//
// R6 = R4 structure (UNROLL=4, exact tiling, block-uniform W/b) with
// __ldcs ONLY on the x stream. Rationale: across graph replays, out's
// dirty lines can persist in the 126 MB L2 and be overwritten without
// DRAM writeback — but only if the x read stream (one-touch, zero reuse)
// doesn't evict them. Evict-first x reads protect the dirty out set and
// should cut per-run DRAM write traffic ~2x. Stores stay DEFAULT (R3
// showed __stcs on out is harmful: it forces early writebacks).

#define UNROLL 4
#define THREADS 256

__global__ void __launch_bounds__(THREADS) plt_exact(
        const float4* __restrict__ x4,
        const float4* __restrict__ W4,
        const float2* __restrict__ b2,
        float4* __restrict__ out4) {
    // Block covers quads [blockIdx.x*1024, +1024) = edges [blockIdx.x*4, +4).
    int base = blockIdx.x * (THREADS * UNROLL) + threadIdx.x;
    int ebase = blockIdx.x * UNROLL;          // block-uniform

    // Front-batched x loads: 4 independent LDG.128, evict-first (no reuse).
    float4 xv[UNROLL];
    #pragma unroll
    for (int k = 0; k < UNROLL; k++)
        xv[k] = __ldcs(x4 + base + k * THREADS);

    // Block-uniform W/b loads, default caching (reused across the grid).
    float4 wv[UNROLL];
    float2 bv[UNROLL];
    #pragma unroll
    for (int k = 0; k < UNROLL; k++) {
        wv[k] = __ldg(W4 + ebase + k);
        bv[k] = __ldg(b2 + ebase + k);
    }

    #pragma unroll
    for (int k = 0; k < UNROLL; k++) {
        float4 o;
        o.x = fmaf(xv[k].x, wv[k].x, fmaf(xv[k].y, wv[k].y, bv[k].x));
        o.y = fmaf(xv[k].x, wv[k].z, fmaf(xv[k].y, wv[k].w, bv[k].y));
        o.z = fmaf(xv[k].z, wv[k].x, fmaf(xv[k].w, wv[k].y, bv[k].x));
        o.w = fmaf(xv[k].z, wv[k].z, fmaf(xv[k].w, wv[k].w, bv[k].y));
        out4[base + k * THREADS] = o;   // default store: let it sit dirty in L2
    }
}

// Guarded fallback for shapes that don't tile exactly (not hit for E=50000).
__global__ void __launch_bounds__(THREADS) plt_generic(
        const float4* __restrict__ x4,
        const float4* __restrict__ W4,
        const float2* __restrict__ b2,
        float4* __restrict__ out4,
        int total_quads,
        int log2_quads_per_edge) {
    int i = blockIdx.x * THREADS + threadIdx.x;
    if (i >= total_quads) return;
    int e = i >> log2_quads_per_edge;
    float4 xv = __ldcs(x4 + i);
    float4 wv = __ldg(W4 + e);
    float2 bv = __ldg(b2 + e);
    float4 o;
    o.x = fmaf(xv.x, wv.x, fmaf(xv.y, wv.y, bv.x));
    o.y = fmaf(xv.x, wv.z, fmaf(xv.y, wv.w, bv.y));
    o.z = fmaf(xv.z, wv.x, fmaf(xv.w, wv.y, bv.x));
    o.w = fmaf(xv.z, wv.z, fmaf(xv.w, wv.w, bv.y));
    out4[i] = o;
}

extern "C" void kernel_launch(void* const* d_in, const int* in_sizes, int n_in,
                              void* d_out, int out_size) {
    const float* x = (const float*)d_in[0];   // [E, B, N]
    const float* W = (const float*)d_in[1];   // [E, O, N]
    const float* b = (const float*)d_in[2];   // [E, O]

    int E = in_sizes[2] / 2;                  // 50000
    int per_edge = in_sizes[0] / E;           // B*N = 1024 floats
    int quads_per_edge = per_edge / 4;        // 256
    int total_quads = in_sizes[0] / 4;        // 12.8M

    int quads_per_block = THREADS * UNROLL;   // 1024

    if (quads_per_edge == THREADS && total_quads % quads_per_block == 0) {
        int blocks = total_quads / quads_per_block;   // 12500
        plt_exact<<<blocks, THREADS>>>((const float4*)x, (const float4*)W,
                                       (const float2*)b, (float4*)d_out);
    } else {
        int log2_q = 0;
        while ((1 << log2_q) < quads_per_edge) log2_q++;
        int blocks = (total_quads + THREADS - 1) / THREADS;
        plt_generic<<<blocks, THREADS>>>((const float4*)x, (const float4*)W,
                                         (const float2*)b, (float4*)d_out,
                                         total_quads, log2_q);
    }
}

// round 7
// speedup vs baseline: 1.0269x; 1.0269x over previous
#include <cuda_runtime.h>

// out[e,b,o] = sum_n x[e,b,n] * W[e,o,n] + b[e,o]
// E=50000, B=512, N=2, O=2. Pure HBM streaming (~411 MB logical traffic).
//
// R7 = R4 (the proven-best memory shape: UNROLL=4 front-batched LDG.128,
// DEFAULT cache ops — every .cs variant regressed; block-uniform W/b;
// exact tiling, zero predicates) with THREADS 256 -> 512.
// Block covers 2048 quads = exactly 8 edges; 6250 blocks.

#define UNROLL 4
#define THREADS 512
#define EDGES_PER_BLOCK 8   // (THREADS * UNROLL) / 256 quads-per-edge

__global__ void __launch_bounds__(THREADS) plt_exact(
        const float4* __restrict__ x4,
        const float4* __restrict__ W4,
        const float2* __restrict__ b2,
        float4* __restrict__ out4) {
    int base = blockIdx.x * (THREADS * UNROLL) + threadIdx.x;
    // Each unroll chunk of 512 threads spans exactly 2 edges; the edge for
    // chunk k depends only on (blockIdx, threadIdx>=256, k) — cheap and
    // warp-uniform.
    int half = threadIdx.x >> 8;                       // 0 or 1 (warp-uniform)
    int ebase = blockIdx.x * EDGES_PER_BLOCK + half;   // edge of chunk 0

    // Front-batched x loads: 4 independent LDG.128, default cache op.
    float4 xv[UNROLL];
    #pragma unroll
    for (int k = 0; k < UNROLL; k++)
        xv[k] = __ldg(x4 + base + k * THREADS);

    // Warp-uniform W/b loads (2 edges advance per chunk).
    float4 wv[UNROLL];
    float2 bv[UNROLL];
    #pragma unroll
    for (int k = 0; k < UNROLL; k++) {
        wv[k] = __ldg(W4 + ebase + 2 * k);
        bv[k] = __ldg(b2 + ebase + 2 * k);
    }

    #pragma unroll
    for (int k = 0; k < UNROLL; k++) {
        float4 o;
        o.x = fmaf(xv[k].x, wv[k].x, fmaf(xv[k].y, wv[k].y, bv[k].x));
        o.y = fmaf(xv[k].x, wv[k].z, fmaf(xv[k].y, wv[k].w, bv[k].y));
        o.z = fmaf(xv[k].z, wv[k].x, fmaf(xv[k].w, wv[k].y, bv[k].x));
        o.w = fmaf(xv[k].z, wv[k].z, fmaf(xv[k].w, wv[k].w, bv[k].y));
        out4[base + k * THREADS] = o;
    }
}

// Guarded fallback for shapes that don't tile exactly (not hit for E=50000).
__global__ void __launch_bounds__(256) plt_generic(
        const float4* __restrict__ x4,
        const float4* __restrict__ W4,
        const float2* __restrict__ b2,
        float4* __restrict__ out4,
        int total_quads,
        int log2_quads_per_edge) {
    int i = blockIdx.x * 256 + threadIdx.x;
    if (i >= total_quads) return;
    int e = i >> log2_quads_per_edge;
    float4 xv = __ldg(x4 + i);
    float4 wv = __ldg(W4 + e);
    float2 bv = __ldg(b2 + e);
    float4 o;
    o.x = fmaf(xv.x, wv.x, fmaf(xv.y, wv.y, bv.x));
    o.y = fmaf(xv.x, wv.z, fmaf(xv.y, wv.w, bv.y));
    o.z = fmaf(xv.z, wv.x, fmaf(xv.w, wv.y, bv.x));
    o.w = fmaf(xv.z, wv.z, fmaf(xv.w, wv.w, bv.y));
    out4[i] = o;
}

extern "C" void kernel_launch(void* const* d_in, const int* in_sizes, int n_in,
                              void* d_out, int out_size) {
    const float* x = (const float*)d_in[0];   // [E, B, N]
    const float* W = (const float*)d_in[1];   // [E, O, N]
    const float* b = (const float*)d_in[2];   // [E, O]

    int E = in_sizes[2] / 2;                  // 50000
    int per_edge = in_sizes[0] / E;           // B*N = 1024 floats
    int quads_per_edge = per_edge / 4;        // 256
    int total_quads = in_sizes[0] / 4;        // 12.8M

    int quads_per_block = THREADS * UNROLL;   // 2048

    // Fast path: 256 quads per edge (so each 256-thread half-chunk = one
    // edge) and exact grid tiling.
    if (quads_per_edge == 256 && total_quads % quads_per_block == 0) {
        int blocks = total_quads / quads_per_block;   // 6250
        plt_exact<<<blocks, THREADS>>>((const float4*)x, (const float4*)W,
                                       (const float2*)b, (float4*)d_out);
    } else {
        int log2_q = 0;
        while ((1 << log2_q) < quads_per_edge) log2_q++;
        int blocks = (total_quads + 255) / 256;
        plt_generic<<<blocks, 256>>>((const float4*)x, (const float4*)W,
                                     (const float2*)b, (float4*)d_out,
                                     total_quads, log2_q);
    }
}